// round 1
// baseline (speedup 1.0000x reference)
#include <cuda_runtime.h>
#include <cstdint>

// Problem constants
static constexpr int B = 2, N = 4, D = 48, H = 28, W = 60, C = 64;
static constexpr int DOWNSAMPLE = 8;
static constexpr int NX = 192, NY = 192, NZ = 1;
static constexpr float F_BEV = 4.0f;           // 1/SCALE
static constexpr float CX_BEV = 96.0f;         // NX/2 + OFFSETX
static constexpr float CY_BEV = 96.0f;         // NY/2
static constexpr float DMIN = 2.0f, DSTEP = 1.0f;

static constexpr int NPTS = B * N * D * H * W;        // 645120
static constexpr int NVOX = B * NZ * NY * NX;         // 73728
static constexpr int STAGE_ELEMS = NVOX * C;          // 4,718,592 floats

// Scratch: channels-last accumulation buffer + per-(b,n) geometry (9 combine + 3 trans)
__device__ __align__(16) float g_stage[STAGE_ELEMS];
__device__ float g_geom[B * N * 12];

// ---------------------------------------------------------------------------
// Kernel 1: zero staging buffer; block 0 also precomputes combine = R @ inv(K)
// ---------------------------------------------------------------------------
__global__ void zero_and_precompute(const float* __restrict__ intr,
                                    const float* __restrict__ pose) {
    // zero with float4 stores
    int idx = blockIdx.x * blockDim.x + threadIdx.x;
    float4* s4 = reinterpret_cast<float4*>(g_stage);
    if (idx < STAGE_ELEMS / 4) {
        s4[idx] = make_float4(0.f, 0.f, 0.f, 0.f);
    }
    if (blockIdx.x == 0 && threadIdx.x < B * N) {
        int i = threadIdx.x;
        const float* K = intr + i * 9;
        float a = K[0], b = K[1], c = K[2];
        float d = K[3], e = K[4], f = K[5];
        float g = K[6], h = K[7], ii = K[8];
        float A  = e * ii - f * h;
        float Bc = f * g - d * ii;
        float Cc = d * h - e * g;
        float det = a * A + b * Bc + c * Cc;
        float inv_det = 1.0f / det;
        float inv[9];
        inv[0] = A * inv_det;            inv[1] = (c * h - b * ii) * inv_det; inv[2] = (b * f - c * e) * inv_det;
        inv[3] = Bc * inv_det;           inv[4] = (a * ii - c * g) * inv_det; inv[5] = (c * d - a * f) * inv_det;
        inv[6] = Cc * inv_det;           inv[7] = (b * g - a * h) * inv_det;  inv[8] = (a * e - b * d) * inv_det;
        const float* P = pose + i * 16;  // 4x4 row-major
        // combine = R(3x3 of pose) @ invK
        for (int r = 0; r < 3; r++) {
            for (int cc = 0; cc < 3; cc++) {
                float s = 0.f;
                for (int k = 0; k < 3; k++) s += P[r * 4 + k] * inv[k * 3 + cc];
                g_geom[i * 12 + r * 3 + cc] = s;
            }
            g_geom[i * 12 + 9 + r] = P[r * 4 + 3];  // translation
        }
    }
}

// ---------------------------------------------------------------------------
// Kernel 2: scatter-add. One thread per (point, channel-quad): 16 threads/point.
// Index computed first; x read + red.global.add.v4.f32 only if kept.
// ---------------------------------------------------------------------------
__global__ void scatter_kernel(const float* __restrict__ x) {
    int gtid = blockIdx.x * blockDim.x + threadIdx.x;
    if (gtid >= NPTS * 16) return;
    int pid = gtid >> 4;
    int q = gtid & 15;

    int w  = pid % W;
    int t1 = pid / W;
    int h  = t1 % H;
    int t2 = t1 / H;
    int dd = t2 % D;
    int t3 = t2 / D;
    int n  = t3 % N;
    int b  = t3 / N;

    const float* cm = g_geom + (b * N + n) * 12;

    // frustum point (matches jnp.linspace / arange in f32)
    const float STEPX = (float)(W * DOWNSAMPLE - 1) / (float)(W - 1);
    const float STEPY = (float)(H * DOWNSAMPLE - 1) / (float)(H - 1);
    float dep = DMIN + (float)dd * DSTEP;
    float u = (float)w * STEPX;
    float v = (float)h * STEPY;
    float px = u * dep, py = v * dep, pz = dep;

    float gxf = fmaf(cm[0], px, fmaf(cm[1], py, fmaf(cm[2], pz, cm[9])));
    float gyf = fmaf(cm[3], px, fmaf(cm[4], py, fmaf(cm[5], pz, cm[10])));
    float gzf = fmaf(cm[6], px, fmaf(cm[7], py, fmaf(cm[8], pz, cm[11])));

    int gx = (int)(gxf * F_BEV + CX_BEV);   // trunc toward zero == jnp astype(int32)
    int gy = (int)(gyf * F_BEV + CY_BEV);
    int gz = (int)((gzf + 10.0f) / 20.0f);

    if (gx < 0 || gx >= NX || gy < 0 || gy >= NY || gz < 0 || gz >= NZ) return;

    int voxel = ((b * NZ + gz) * NY + gy) * NX + gx;
    const float4 val = *reinterpret_cast<const float4*>(x + (size_t)pid * C + q * 4);
    float* dst = g_stage + (size_t)voxel * C + q * 4;
    asm volatile("red.global.add.v4.f32 [%0], {%1, %2, %3, %4};"
                 :: "l"(dst), "f"(val.x), "f"(val.y), "f"(val.z), "f"(val.w)
                 : "memory");
}

// ---------------------------------------------------------------------------
// Kernel 3: transpose stage (B, NZ, NY, NX, C) -> out (B, NZ*C, NY, NX)
// 32x32 shared-memory tile over (x, c); both sides coalesced.
// ---------------------------------------------------------------------------
__global__ void transpose_kernel(float* __restrict__ out) {
    __shared__ float tile[32][33];
    int xt = blockIdx.x % (NX / 32);       // x tile
    int ct = blockIdx.x / (NX / 32);       // c tile
    int y  = blockIdx.y;
    int bz = blockIdx.z;                   // b*NZ + z
    int b  = bz / NZ;
    int z  = bz % NZ;

    // load: consecutive threadIdx.x -> consecutive c (coalesced stage read)
    {
        int c    = ct * 32 + threadIdx.x;
        int xcol = xt * 32 + threadIdx.y;
        size_t sidx = ((size_t)((b * NZ + z) * NY + y) * NX + xcol) * C + c;
        tile[threadIdx.y][threadIdx.x] = g_stage[sidx];
    }
    __syncthreads();
    // store: consecutive threadIdx.x -> consecutive x (coalesced out write)
    {
        int xcol = xt * 32 + threadIdx.x;
        int c    = ct * 32 + threadIdx.y;
        size_t oidx = ((size_t)(b * (NZ * C) + z * C + c) * NY + y) * NX + xcol;
        out[oidx] = tile[threadIdx.x][threadIdx.y];
    }
}

// ---------------------------------------------------------------------------
extern "C" void kernel_launch(void* const* d_in, const int* in_sizes, int n_in,
                              void* d_out, int out_size) {
    const float* x    = (const float*)d_in[0];
    const float* intr = (const float*)d_in[1];
    const float* pose = (const float*)d_in[2];
    float* out = (float*)d_out;

    {
        int threads = 256;
        int blocks = (STAGE_ELEMS / 4 + threads - 1) / threads;  // 4608
        zero_and_precompute<<<blocks, threads>>>(intr, pose);
    }
    {
        int threads = 256;
        int total = NPTS * 16;                                   // 10,321,920
        int blocks = (total + threads - 1) / threads;            // 40320
        scatter_kernel<<<blocks, threads>>>(x);
    }
    {
        dim3 grid((NX / 32) * (C / 32), NY, B * NZ);             // (12, 192, 2)
        dim3 block(32, 32);
        transpose_kernel<<<grid, block>>>(out);
    }
}

// round 3
// speedup vs baseline: 1.4214x; 1.4214x over previous
#include <cuda_runtime.h>
#include <cstdint>

// Problem constants
static constexpr int B = 2, N = 4, D = 48, H = 28, W = 60, C = 64;
static constexpr int DOWNSAMPLE = 8;
static constexpr int NX = 192, NY = 192, NZ = 1;
static constexpr float F_BEV = 4.0f;           // 1/SCALE
static constexpr float CX_BEV = 96.0f;         // NX/2 + OFFSETX
static constexpr float CY_BEV = 96.0f;         // NY/2
static constexpr float DMIN = 2.0f, DSTEP = 1.0f;

static constexpr int NVOX = B * NZ * NY * NX;         // 73728
static constexpr int STAGE_ELEMS = NVOX * C;          // 4,718,592 floats

// Channels-last accumulation buffer (L2-resident, 18.9 MB)
__device__ __align__(16) float g_stage[STAGE_ELEMS];

// ---------------------------------------------------------------------------
// Kernel 0: zero the staging buffer (float4 grid-stride).
// ---------------------------------------------------------------------------
__global__ void zero_stage() {
    float4* s4 = reinterpret_cast<float4*>(g_stage);
    int n4 = STAGE_ELEMS / 4;
    for (int i = blockIdx.x * blockDim.x + threadIdx.x; i < n4;
         i += gridDim.x * blockDim.x) {
        s4[i] = make_float4(0.f, 0.f, 0.f, 0.f);
    }
}

// ---------------------------------------------------------------------------
// Kernel 1: scatter. One thread per (b,n,d,w, channel-quad). Loops over h,
// run-length accumulating in a register float4 while the voxel index is
// unchanged, flushing with red.global.add.v4.f32 only on voxel change / end.
// Geometry (combine = R @ inv(K), trans) is computed per-block in smem.
// ---------------------------------------------------------------------------
__global__ void scatter_kernel(const float* __restrict__ x,
                               const float* __restrict__ intr,
                               const float* __restrict__ pose) {
    __shared__ float s_geom[B * N * 12];

    if (threadIdx.x < B * N) {
        int i = threadIdx.x;
        const float* K = intr + i * 9;
        float a = K[0], b = K[1], c = K[2];
        float d = K[3], e = K[4], f = K[5];
        float g = K[6], h = K[7], ii = K[8];
        float A  = e * ii - f * h;
        float Bc = f * g - d * ii;
        float Cc = d * h - e * g;
        float inv_det = 1.0f / (a * A + b * Bc + c * Cc);
        float inv[9];
        inv[0] = A * inv_det;  inv[1] = (c * h - b * ii) * inv_det; inv[2] = (b * f - c * e) * inv_det;
        inv[3] = Bc * inv_det; inv[4] = (a * ii - c * g) * inv_det; inv[5] = (c * d - a * f) * inv_det;
        inv[6] = Cc * inv_det; inv[7] = (b * g - a * h) * inv_det;  inv[8] = (a * e - b * d) * inv_det;
        const float* P = pose + i * 16;
        for (int r = 0; r < 3; r++) {
            for (int cc = 0; cc < 3; cc++) {
                float s = 0.f;
                for (int k = 0; k < 3; k++) s += P[r * 4 + k] * inv[k * 3 + cc];
                s_geom[i * 12 + r * 3 + cc] = s;
            }
            s_geom[i * 12 + 9 + r] = P[r * 4 + 3];
        }
    }
    __syncthreads();

    int gtid = blockIdx.x * blockDim.x + threadIdx.x;
    if (gtid >= B * N * D * W * 16) return;
    int q   = gtid & 15;          // channel quad
    int col = gtid >> 4;          // (b,n,d,w) column
    int w  = col % W;
    int r1 = col / W;
    int dd = r1 % D;
    int r2 = r1 / D;
    int n  = r2 % N;
    int b  = r2 / N;

    const float* cm = s_geom + (b * N + n) * 12;
    float cm0 = cm[0], cm1 = cm[1], cm2 = cm[2], cm9  = cm[9];
    float cm3 = cm[3], cm4 = cm[4], cm5 = cm[5], cm10 = cm[10];
    float cm6 = cm[6], cm7 = cm[7], cm8 = cm[8], cm11 = cm[11];

    const float STEPX = (float)(W * DOWNSAMPLE - 1) / (float)(W - 1);
    const float STEPY = (float)(H * DOWNSAMPLE - 1) / (float)(H - 1);
    float dep = DMIN + (float)dd * DSTEP;
    float u  = (float)w * STEPX;
    float px = u * dep;
    float pz = dep;

    const float* xp = x + ((size_t)(((b * N + n) * D + dd) * H) * W + w) * C + q * 4;

    int curv = -1;
    float4 acc = make_float4(0.f, 0.f, 0.f, 0.f);

    #pragma unroll 4
    for (int h = 0; h < H; h++) {
        float v  = (float)h * STEPY;
        float py = v * dep;
        // same fmaf chain as the verified round-1 kernel (bin-boundary stability)
        float gxf = fmaf(cm0, px, fmaf(cm1, py, fmaf(cm2, pz, cm9)));
        float gyf = fmaf(cm3, px, fmaf(cm4, py, fmaf(cm5, pz, cm10)));
        float gzf = fmaf(cm6, px, fmaf(cm7, py, fmaf(cm8, pz, cm11)));

        int gx = (int)(gxf * F_BEV + CX_BEV);   // trunc toward zero == astype(int32)
        int gy = (int)(gyf * F_BEV + CY_BEV);
        int gz = (int)((gzf + 10.0f) / 20.0f);

        bool kept = (gx >= 0) & (gx < NX) & (gy >= 0) & (gy < NY) & (gz >= 0) & (gz < NZ);
        if (kept) {
            int voxel = ((b * NZ + gz) * NY + gy) * NX + gx;
            const float4 val = *reinterpret_cast<const float4*>(xp);
            if (voxel == curv) {
                acc.x += val.x; acc.y += val.y; acc.z += val.z; acc.w += val.w;
            } else {
                if (curv >= 0) {
                    float* dst = g_stage + (size_t)curv * C + q * 4;
                    asm volatile("red.global.add.v4.f32 [%0], {%1, %2, %3, %4};"
                                 :: "l"(dst), "f"(acc.x), "f"(acc.y), "f"(acc.z), "f"(acc.w)
                                 : "memory");
                }
                curv = voxel;
                acc = val;
            }
        }
        xp += W * C;
    }
    if (curv >= 0) {
        float* dst = g_stage + (size_t)curv * C + q * 4;
        asm volatile("red.global.add.v4.f32 [%0], {%1, %2, %3, %4};"
                     :: "l"(dst), "f"(acc.x), "f"(acc.y), "f"(acc.z), "f"(acc.w)
                     : "memory");
    }
}

// ---------------------------------------------------------------------------
// Kernel 2: transpose stage (B, NZ, NY, NX, C) -> out (B, NZ*C, NY, NX).
// 64x64 tile (c covers full C=64), float4 on both global sides.
// ---------------------------------------------------------------------------
__global__ void transpose_kernel(float* __restrict__ out) {
    __shared__ float tile[64][65];   // tile[c][x]
    int xt = blockIdx.x;             // 0..NX/64-1
    int y  = blockIdx.y;
    int bz = blockIdx.z;             // b*NZ + z
    int t  = threadIdx.x;            // 256 threads

    const float4* src = reinterpret_cast<const float4*>(
        g_stage + ((size_t)(bz * NY + y) * NX + xt * 64) * C);
    #pragma unroll
    for (int p = 0; p < 4; p++) {
        int e  = p * 256 + t;
        int xr = e >> 4;             // x within tile
        int cq = e & 15;             // c quad
        float4 v = src[xr * 16 + cq];
        tile[cq * 4 + 0][xr] = v.x;
        tile[cq * 4 + 1][xr] = v.y;
        tile[cq * 4 + 2][xr] = v.z;
        tile[cq * 4 + 3][xr] = v.w;
    }
    __syncthreads();
    int b = bz / NZ, z = bz % NZ;
    #pragma unroll
    for (int p = 0; p < 4; p++) {
        int e  = p * 256 + t;
        int cr = e >> 4;             // channel row
        int xq = e & 15;             // x quad
        float4 v = make_float4(tile[cr][xq * 4 + 0], tile[cr][xq * 4 + 1],
                               tile[cr][xq * 4 + 2], tile[cr][xq * 4 + 3]);
        float4* dstv = reinterpret_cast<float4*>(
            out + ((size_t)((b * NZ + z) * C + cr) * NY + y) * NX + xt * 64);
        dstv[xq] = v;
    }
}

// ---------------------------------------------------------------------------
extern "C" void kernel_launch(void* const* d_in, const int* in_sizes, int n_in,
                              void* d_out, int out_size) {
    const float* x    = (const float*)d_in[0];
    const float* intr = (const float*)d_in[1];
    const float* pose = (const float*)d_in[2];
    float* out = (float*)d_out;

    zero_stage<<<1184, 256>>>();                         // 18.9 MB of float4 stores

    {
        int total = B * N * D * W * 16;                  // 368,640 threads
        int threads = 256;
        int blocks = (total + threads - 1) / threads;    // 1440
        scatter_kernel<<<blocks, threads>>>(x, intr, pose);
    }
    {
        dim3 grid(NX / 64, NY, B * NZ);                  // (3, 192, 2)
        transpose_kernel<<<grid, 256>>>(out);
    }
}

// round 7
// speedup vs baseline: 2.2940x; 1.6139x over previous
#include <cuda_runtime.h>
#include <cstdint>

// Problem constants
static constexpr int B = 2, N = 4, D = 48, H = 28, W = 60, C = 64;
static constexpr int DOWNSAMPLE = 8;
static constexpr int NX = 192, NY = 192, NZ = 1;
static constexpr float F_BEV = 4.0f;           // 1/SCALE
static constexpr float CX_BEV = 96.0f;         // NX/2 + OFFSETX
static constexpr float CY_BEV = 96.0f;         // NY/2
static constexpr float DMIN = 2.0f, DSTEP = 1.0f;

static constexpr int NCOL  = B * N * D * W;    // 23040 columns (b,n,d,w)
static constexpr int PLANE = NY * NX;          // 36864
static constexpr int OUT_ELEMS = B * NZ * C * PLANE;  // 4,718,592 floats
static constexpr int OUT_F4   = OUT_ELEMS / 4;        // 1,179,648 float4

// ---------------------------------------------------------------------------
// Kernel 0: zero d_out (output is the accumulator). Grid-stride float4 loop
// (covers the FULL buffer — R5's fixed-count version only covered 1/4).
// ---------------------------------------------------------------------------
__global__ void zero_out(float* __restrict__ out) {
    float4* o4 = reinterpret_cast<float4*>(out);
    const float4 z = make_float4(0.f, 0.f, 0.f, 0.f);
    for (int i = blockIdx.x * blockDim.x + threadIdx.x; i < OUT_F4;
         i += gridDim.x * blockDim.x) {
        o4[i] = z;
    }
}

// ---------------------------------------------------------------------------
// Kernel 1: scatter directly into out (B, C, NY, NX).
// Thread = (column cid, channel-quad q). Warp = 2 columns x 16 quads.
// Phase 1: lane computes voxel(own col, h=q) and voxel(own col, h=q+16)
//          -> geometry evaluated 2x per lane instead of 28x.
// Phase 2: h loop; voxel[h] fetched by one shuffle; run-length accumulate
//          float4 in registers; flush = 4 scalar red.add.f32 (channel-strided).
// (verified correct on first-call in R5: rel_err 2.38e-7)
// ---------------------------------------------------------------------------
__global__ __launch_bounds__(256) void scatter_kernel(
        const float* __restrict__ x,
        const float* __restrict__ intr,
        const float* __restrict__ pose,
        float* __restrict__ out) {
    __shared__ float s_geom[B * N * 12];

    if (threadIdx.x < B * N) {
        int i = threadIdx.x;
        const float* K = intr + i * 9;
        float a = K[0], b = K[1], c = K[2];
        float d = K[3], e = K[4], f = K[5];
        float g = K[6], h = K[7], ii = K[8];
        float A  = e * ii - f * h;
        float Bc = f * g - d * ii;
        float Cc = d * h - e * g;
        float inv_det = 1.0f / (a * A + b * Bc + c * Cc);
        float inv[9];
        inv[0] = A * inv_det;  inv[1] = (c * h - b * ii) * inv_det; inv[2] = (b * f - c * e) * inv_det;
        inv[3] = Bc * inv_det; inv[4] = (a * ii - c * g) * inv_det; inv[5] = (c * d - a * f) * inv_det;
        inv[6] = Cc * inv_det; inv[7] = (b * g - a * h) * inv_det;  inv[8] = (a * e - b * d) * inv_det;
        const float* P = pose + i * 16;
        for (int r = 0; r < 3; r++) {
            for (int cc = 0; cc < 3; cc++) {
                float s = 0.f;
                for (int k = 0; k < 3; k++) s += P[r * 4 + k] * inv[k * 3 + cc];
                s_geom[i * 12 + r * 3 + cc] = s;
            }
            s_geom[i * 12 + 9 + r] = P[r * 4 + 3];
        }
    }
    __syncthreads();

    const int gtid = blockIdx.x * 256 + threadIdx.x;   // 0 .. NCOL*16-1 (exact)
    const int lane = threadIdx.x & 31;
    const int q    = gtid & 15;
    const int cid  = gtid >> 4;

    // decode column (b,n,d,w):  cid = ((b*N+n)*D + d)*W + w
    const int w   = cid % W;
    const int bnd = cid / W;              // (b*N+n)*D + d
    const int dd  = bnd % D;
    const int bn  = bnd / D;              // b*N + n
    const int b   = bn >> 2;              // /N

    const float* cm = s_geom + bn * 12;
    const float cm0 = cm[0], cm1 = cm[1], cm2 = cm[2], cm9  = cm[9];
    const float cm3 = cm[3], cm4 = cm[4], cm5 = cm[5], cm10 = cm[10];
    const float cm6 = cm[6], cm7 = cm[7], cm8 = cm[8], cm11 = cm[11];

    const float STEPX = (float)(W * DOWNSAMPLE - 1) / (float)(W - 1);
    const float STEPY = (float)(H * DOWNSAMPLE - 1) / (float)(H - 1);
    const float dep = DMIN + (float)dd * DSTEP;
    const float px  = ((float)w * STEPX) * dep;
    const float pz  = dep;

    // --- Phase 1: this lane evaluates geometry for h = q and h = q+16 ---
    // identical fmaf chains to the verified kernels (bin-boundary stability)
    auto voxel_at = [&](int h) -> int {
        float v  = (float)h * STEPY;
        float py = v * dep;
        float gxf = fmaf(cm0, px, fmaf(cm1, py, fmaf(cm2, pz, cm9)));
        float gyf = fmaf(cm3, px, fmaf(cm4, py, fmaf(cm5, pz, cm10)));
        float gzf = fmaf(cm6, px, fmaf(cm7, py, fmaf(cm8, pz, cm11)));
        int gx = (int)(gxf * F_BEV + CX_BEV);     // trunc == astype(int32)
        int gy = (int)(gyf * F_BEV + CY_BEV);
        int gz = (int)((gzf + 10.0f) / 20.0f);
        bool kept = (gx >= 0) & (gx < NX) & (gy >= 0) & (gy < NY) & (gz >= 0) & (gz < NZ);
        return kept ? (gz * NY + gy) * NX + gx : -1;   // NZ=1 -> gz*NY*NX folds in
    };
    int v1 = voxel_at(q);
    int v2 = (q < 12) ? voxel_at(q + 16) : -1;

    // --- warp early-exit: nothing kept in either column of this warp ---
    unsigned ball = __ballot_sync(0xffffffffu, (v1 >= 0) | (v2 >= 0));
    if (ball == 0u) return;

    // --- Phase 2: data loop ---
    const float* xp = x + ((size_t)(bnd * H * W) + w) * C + q * 4;  // h=0 row
    const int shfl_base = lane & 16;
    float* const outbase = out + ((size_t)b * C + q * 4) * PLANE;

    int curv = -1;
    float4 acc = make_float4(0.f, 0.f, 0.f, 0.f);

    #pragma unroll 4
    for (int h = 0; h < H; h++) {
        int vox = __shfl_sync(0xffffffffu, (h < 16) ? v1 : v2, shfl_base | (h & 15));
        if (vox >= 0) {
            const float4 val = *reinterpret_cast<const float4*>(xp);
            if (vox == curv) {
                acc.x += val.x; acc.y += val.y; acc.z += val.z; acc.w += val.w;
            } else {
                if (curv >= 0) {
                    float* dst = outbase + curv;
                    asm volatile("red.global.add.f32 [%0], %1;" :: "l"(dst),             "f"(acc.x) : "memory");
                    asm volatile("red.global.add.f32 [%0], %1;" :: "l"(dst + PLANE),     "f"(acc.y) : "memory");
                    asm volatile("red.global.add.f32 [%0], %1;" :: "l"(dst + 2 * PLANE), "f"(acc.z) : "memory");
                    asm volatile("red.global.add.f32 [%0], %1;" :: "l"(dst + 3 * PLANE), "f"(acc.w) : "memory");
                }
                curv = vox;
                acc = val;
            }
        }
        xp += W * C;
    }
    if (curv >= 0) {
        float* dst = outbase + curv;
        asm volatile("red.global.add.f32 [%0], %1;" :: "l"(dst),             "f"(acc.x) : "memory");
        asm volatile("red.global.add.f32 [%0], %1;" :: "l"(dst + PLANE),     "f"(acc.y) : "memory");
        asm volatile("red.global.add.f32 [%0], %1;" :: "l"(dst + 2 * PLANE), "f"(acc.z) : "memory");
        asm volatile("red.global.add.f32 [%0], %1;" :: "l"(dst + 3 * PLANE), "f"(acc.w) : "memory");
    }
}

// ---------------------------------------------------------------------------
extern "C" void kernel_launch(void* const* d_in, const int* in_sizes, int n_in,
                              void* d_out, int out_size) {
    const float* x    = (const float*)d_in[0];
    const float* intr = (const float*)d_in[1];
    const float* pose = (const float*)d_in[2];
    float* out = (float*)d_out;

    // grid-stride: 1184 blocks x 256 threads covers all OUT_F4 float4
    zero_out<<<1184, 256>>>(out);

    // NCOL*16 = 368,640 threads = 1440 blocks x 256 (exact)
    scatter_kernel<<<1440, 256>>>(x, intr, pose, out);
}